// round 16
// baseline (speedup 1.0000x reference)
#include <cuda_runtime.h>
#include <cstdint>

// ============================================================================
// Problem constants
// ============================================================================
static constexpr int BB   = 8192;
static constexpr int IN_  = 2048;
static constexpr int OUT_ = 3072;
static constexpr int S_   = 8;

static constexpr int TM   = 128;
static constexpr int TN   = 256;
static constexpr int KC   = 32;            // K per chunk
static constexpr int NKC  = IN_ / KC;      // 64
static constexpr int NT_N = OUT_ / TN;     // 12
static constexpr int MAX_TILES = 72;
static constexpr int NTHREADS = 256;       // 8 warps: 2(m) x 4(n), warp 64x64
static constexpr int STAGES = 4;

static constexpr int A_BYTES = TM * KC * 4;              // 16384
static constexpr int B_BYTES = KC * TN * 4;              // 32768
static constexpr int STAGE_BYTES = A_BYTES + B_BYTES;    // 49152
static constexpr int SMEM_TOTAL  = STAGES * STAGE_BYTES; // 196608

// ============================================================================
// Device globals
// ============================================================================
__device__ int g_tile_subject[MAX_TILES];
__device__ int g_perm[MAX_TILES * TM];

// ============================================================================
// Helpers
// ============================================================================
#define DI __device__ __forceinline__

DI unsigned smem_u32(const void* p) {
    unsigned a;
    asm("{ .reg .u64 t; cvta.to.shared.u64 t, %1; cvt.u32.u64 %0, t; }" : "=r"(a) : "l"(p));
    return a;
}
DI unsigned swzA(unsigned o) { return o ^ ((o >> 3) & 0x70u); }
DI unsigned swzB(unsigned o) { return o ^ ((o >> 5) & 0x60u); }

DI void cpasync16(unsigned dst, const void* src) {
    asm volatile("cp.async.cg.shared.global [%0], [%1], 16;"
                 :: "r"(dst), "l"(src) : "memory");
}
// zero-fill variant: src_sz = 16 (copy) or 0 (fill smem with zeros)
DI void cpasync16z(unsigned dst, const void* src, int src_sz) {
    asm volatile("cp.async.cg.shared.global [%0], [%1], 16, %2;"
                 :: "r"(dst), "l"(src), "r"(src_sz) : "memory");
}
DI void cp_commit() { asm volatile("cp.async.commit_group;" ::: "memory"); }
template <int N> DI void cp_wait() {
    asm volatile("cp.async.wait_group %0;" :: "n"(N) : "memory");
}
DI unsigned lds32(unsigned addr) {
    unsigned v;
    asm volatile("ld.shared.b32 %0, [%1];" : "=r"(v) : "r"(addr));
    return v;
}
DI void ldm4(unsigned* r, unsigned addr) {
    asm volatile("ldmatrix.sync.aligned.m8n8.x4.shared.b16 {%0,%1,%2,%3}, [%4];"
                 : "=r"(r[0]), "=r"(r[1]), "=r"(r[2]), "=r"(r[3]) : "r"(addr));
}
DI void mma_tf32(float* d, const unsigned* a, const unsigned* b) {
    asm volatile(
        "mma.sync.aligned.m16n8k8.row.col.f32.tf32.tf32.f32 "
        "{%0,%1,%2,%3}, {%4,%5,%6,%7}, {%8,%9}, {%0,%1,%2,%3};"
        : "+f"(d[0]), "+f"(d[1]), "+f"(d[2]), "+f"(d[3])
        : "r"(a[0]), "r"(a[1]), "r"(a[2]), "r"(a[3]), "r"(b[0]), "r"(b[1]));
}

// ============================================================================
// Setup
// ============================================================================
__global__ void k_setup(const int* __restrict__ sid_raw) {
    __shared__ int nz, counts_s[S_], cursor_s[S_], pad_s[S_];
    const int tid = threadIdx.x;  // 1024
    if (tid == 0) nz = 0;
    if (tid < S_) { counts_s[tid] = 0; cursor_s[tid] = 0; }
    for (int i = tid; i < MAX_TILES * TM; i += 1024) g_perm[i] = -1;
    if (tid < MAX_TILES) g_tile_subject[tid] = -1;
    __syncthreads();
    if (tid < 128 && sid_raw[2 * tid + 1] != 0) atomicOr(&nz, 1);
    __syncthreads();
    const int is64 = (nz == 0);
    int svals[8];
#pragma unroll
    for (int j = 0; j < 8; j++) {
        const int b = tid + j * 1024;
        int s = is64 ? (int)((const long long*)sid_raw)[b] : sid_raw[b];
        s &= (S_ - 1);
        svals[j] = s;
        atomicAdd(&counts_s[s], 1);
    }
    __syncthreads();
    if (tid == 0) {
        int off = 0, tile = 0;
        for (int s = 0; s < S_; s++) {
            pad_s[s] = off;
            const int nt = (counts_s[s] + TM - 1) / TM;
            for (int t = 0; t < nt; t++) g_tile_subject[tile++] = s;
            off += nt * TM;
        }
    }
    __syncthreads();
#pragma unroll
    for (int j = 0; j < 8; j++) {
        const int b = tid + j * 1024;
        const int s = svals[j];
        const int r = atomicAdd(&cursor_s[s], 1);
        g_perm[pad_s[s] + r] = b;
    }
}

// ============================================================================
// Grouped tf32 GEMM (R13 core + main loop unrolled x4: stage indices
// constant-fold per unrolled instance, removing per-iteration address ALU).
// CTA 128x256, 8 warps (2m x 4n), warp 64x64. 4-stage K=32 cp.async ring
// (wait<2>), fragment double-buffer across chunks, early ISSUE at loop top.
// A gathered directly from x through g_perm (padding rows zero-filled via
// cp.async src_size=0). Both per-thread A swizzle destinations precomputed
// (swzA NOT affine under +16 for odd rows); +8192 row offset IS swizzle-safe.
// Grid: blockIdx.x = n-block (fast), blockIdx.y = tile -> A tiles L2-shared.
// ============================================================================
#define LOADG(KS, BUF, ST)                                                         \
    do {                                                                           \
        const unsigned _aco = ((unsigned)((KS) * 32) + acol_f) ^ axor;             \
        _Pragma("unroll")                                                          \
        for (int _ma = 0; _ma < 4; _ma++)                                          \
            ldm4(afr[BUF][_ma],                                                    \
                 (ST) + (unsigned)((wm * 64 + _ma * 16 + arow_f) * 128) + _aco);   \
        const unsigned _br0 = (ST) + (unsigned)A_BYTES                             \
                              + (unsigned)(((KS) * 8 + kk) * 1024);                \
        _Pragma("unroll")                                                          \
        for (int _na = 0; _na < 8; _na++) {                                        \
            const unsigned _co = bbase + (unsigned)(((_na ^ kk) & 7) << 5);        \
            bfr[BUF][_na][0] = lds32(_br0 + _co);                                  \
            bfr[BUF][_na][1] = lds32(_br0 + 4096 + _co);                           \
        }                                                                          \
    } while (0)

#define MMAALL(BUF)                                                                \
    do {                                                                           \
        _Pragma("unroll")                                                          \
        for (int _ma = 0; _ma < 4; _ma++)                                          \
            _Pragma("unroll")                                                      \
            for (int _na = 0; _na < 8; _na++)                                      \
                mma_tf32(acc[_ma][_na], afr[BUF][_ma], bfr[BUF][_na]);             \
    } while (0)

#define ISSUE_CHUNK(ST, KOFF)                                                      \
    do {                                                                           \
        const float* _a0 = asrc0 + (KOFF);                                         \
        const float* _a1 = asrc1 + (KOFF);                                         \
        cpasync16z((ST) + adst00,        _a0,     az0);                            \
        cpasync16z((ST) + adst01,        _a0 + 4, az0);                            \
        cpasync16z((ST) + adst00 + 8192, _a1,     az1);                            \
        cpasync16z((ST) + adst01 + 8192, _a1 + 4, az1);                            \
        const float* _bs = Ws + (size_t)(KOFF) * OUT_ + n_base;                    \
        _Pragma("unroll")                                                          \
        for (int _i = 0; _i < 8; _i++)                                             \
            cpasync16((ST) + (unsigned)A_BYTES + bdst0 + (unsigned)(_i * 4096),    \
                      _bs + boff0 + _i * 4 * OUT_);                                \
    } while (0)

__global__ void __launch_bounds__(NTHREADS, 1)
k_gemm(const float* __restrict__ x, const float* __restrict__ W,
       const float* __restrict__ bias, float* __restrict__ out) {
    extern __shared__ char smem[];
    const int tile = blockIdx.y;
    const int sub = g_tile_subject[tile];
    if (sub < 0) return;

    const int tid  = threadIdx.x;
    const int wid  = tid >> 5;
    const int lane = tid & 31;
    const int q    = lane >> 2;
    const int kk   = lane & 3;
    const int wm   = wid >> 2;
    const int wn   = wid & 3;
    const int m_base = tile * TM;
    const int n_base = blockIdx.x * TN;
    const unsigned sb = smem_u32(smem);

    const float* Ws = W + (size_t)sub * IN_ * OUT_;

    // ---- A gather setup: rows ar0 = tid>>2 and ar0+64, f4 pair (tid&3)*2 ----
    const int ar0 = tid >> 2;
    const int afc = (tid & 3) * 8;              // float offset of first f4
    const int p0g = g_perm[m_base + ar0];
    const int p1g = g_perm[m_base + ar0 + 64];
    const float* asrc0 = x + (size_t)(p0g < 0 ? 0 : p0g) * IN_ + afc;
    const float* asrc1 = x + (size_t)(p1g < 0 ? 0 : p1g) * IN_ + afc;
    const int az0 = (p0g >= 0) ? 16 : 0;
    const int az1 = (p1g >= 0) ? 16 : 0;
    const unsigned abyte0 = (unsigned)(ar0 * 128 + afc * 4);
    const unsigned adst00 = swzA(abyte0);
    const unsigned adst01 = swzA(abyte0 + 16);

    // B affine cp.async bases
    const unsigned bdst0 = swzB((unsigned)((tid >> 6) * 1024 + (tid & 63) * 16));
    const int      boff0 = (tid >> 6) * OUT_ + (tid & 63) * 4;

    // prologue: chunks 0..2 into stages 0..2
#pragma unroll
    for (int c = 0; c < STAGES - 1; c++) {
        ISSUE_CHUNK(sb + (unsigned)c * STAGE_BYTES, c * KC);
        cp_commit();
    }

    float acc[4][8][4];
#pragma unroll
    for (int i = 0; i < 4; i++)
#pragma unroll
        for (int j = 0; j < 8; j++)
#pragma unroll
            for (int c = 0; c < 4; c++) acc[i][j][c] = 0.f;

    // ldmatrix lane geometry (A)
    const int lt = lane >> 3, lr = lane & 7;
    const int arow_f = ((lt & 1) << 3) + lr;
    const unsigned acol_f = (unsigned)((lt >> 1) << 4);
    const unsigned axor = (unsigned)(lr << 4);
    const unsigned bbase = (unsigned)(wn * 256 + q * 4);

    unsigned afr[2][4][4], bfr[2][8][2];

    cp_wait<2>();            // chunk 0 complete
    __syncthreads();
    LOADG(0, 0, sb);         // prime g0 of chunk 0 into buf 0

    // main loop, unrolled x4: stage indices (kc&3, (kc+3)&3, (kc+1)&3) are
    // compile-time constants in each instance -> smem bases fold to immediates.
#pragma unroll 4
    for (int kc = 0; kc < NKC; kc++) {
        const unsigned st = sb + (unsigned)(kc & (STAGES - 1)) * STAGE_BYTES;

        if (kc + STAGES - 1 < NKC) {           // prefetch chunk kc+3 (earliest point)
            const unsigned ns = sb + (unsigned)((kc + STAGES - 1) & (STAGES - 1)) * STAGE_BYTES;
            ISSUE_CHUNK(ns, (kc + STAGES - 1) * KC);
        }
        cp_commit();                           // unconditional: group count exact

        LOADG(1, 1, st);                       // g0
        MMAALL(0);
        LOADG(2, 0, st);                       // g1
        MMAALL(1);
        LOADG(3, 1, st);                       // g2
        MMAALL(0);
        cp_wait<2>();                          // chunk kc+1 complete
        __syncthreads();                       // stage-reuse + visibility barrier
        if (kc + 1 < NKC) {                    // g0 of next chunk under final mma run
            const unsigned ns = sb + (unsigned)((kc + 1) & (STAGES - 1)) * STAGE_BYTES;
            LOADG(0, 0, ns);
        }
        MMAALL(1);                             // g3
    }

    // epilogue: scatter rows through g_perm, add bias
    const float* bias_s = bias + (size_t)sub * OUT_;
    float2 bv[8];
#pragma unroll
    for (int na = 0; na < 8; na++) {
        const int col = n_base + wn * 64 + na * 8 + kk * 2;
        bv[na] = *(const float2*)(bias_s + col);
    }
#pragma unroll
    for (int ma = 0; ma < 4; ma++) {
        const int mr = m_base + wm * 64 + ma * 16 + q;
        const int p0 = g_perm[mr];
        const int p1 = g_perm[mr + 8];
        float* o0 = out + (size_t)(p0 < 0 ? 0 : p0) * OUT_;
        float* o1 = out + (size_t)(p1 < 0 ? 0 : p1) * OUT_;
#pragma unroll
        for (int na = 0; na < 8; na++) {
            const int col = n_base + wn * 64 + na * 8 + kk * 2;
            if (p0 >= 0) {
                float2 v = make_float2(acc[ma][na][0] + bv[na].x,
                                       acc[ma][na][1] + bv[na].y);
                *(float2*)(o0 + col) = v;
            }
            if (p1 >= 0) {
                float2 v = make_float2(acc[ma][na][2] + bv[na].x,
                                       acc[ma][na][3] + bv[na].y);
                *(float2*)(o1 + col) = v;
            }
        }
    }
}

// ============================================================================
// Launch
// ============================================================================
extern "C" void kernel_launch(void* const* d_in, const int* in_sizes, int n_in,
                              void* d_out, int out_size) {
    const float* x    = (const float*)d_in[0];
    const void*  sid  = (const void*)d_in[1];
    const float* W    = (const float*)d_in[2];
    const float* bias = (const float*)d_in[3];
    float* out        = (float*)d_out;

    cudaFuncSetAttribute(k_gemm, cudaFuncAttributeMaxDynamicSharedMemorySize, SMEM_TOTAL);

    k_setup<<<1, 1024>>>((const int*)sid);                  // launch 1
    dim3 gg(NT_N, MAX_TILES);                               // x = n-block, y = tile
    k_gemm<<<gg, NTHREADS, SMEM_TOTAL>>>(x, W, bias, out);  // launch 2
}

// round 17
// speedup vs baseline: 1.0026x; 1.0026x over previous
#include <cuda_runtime.h>
#include <cstdint>

// ============================================================================
// Problem constants
// ============================================================================
static constexpr int BB   = 8192;
static constexpr int IN_  = 2048;
static constexpr int OUT_ = 3072;
static constexpr int S_   = 8;

static constexpr int TM   = 128;
static constexpr int TN   = 256;
static constexpr int KC   = 32;            // K per chunk
static constexpr int NKC  = IN_ / KC;      // 64
static constexpr int NT_N = OUT_ / TN;     // 12
static constexpr int MAX_TILES = 72;
static constexpr int NTHREADS = 256;       // 8 warps: 2(m) x 4(n), warp 64x64
static constexpr int STAGES = 4;

static constexpr int A_BYTES = TM * KC * 4;              // 16384
static constexpr int B_BYTES = KC * TN * 4;              // 32768
static constexpr int STAGE_BYTES = A_BYTES + B_BYTES;    // 49152
static constexpr int SMEM_TOTAL  = STAGES * STAGE_BYTES; // 196608

// ============================================================================
// Device globals
// ============================================================================
__device__ int g_tile_subject[MAX_TILES];
__device__ int g_perm[MAX_TILES * TM];

// ============================================================================
// Helpers
// ============================================================================
#define DI __device__ __forceinline__

DI unsigned smem_u32(const void* p) {
    unsigned a;
    asm("{ .reg .u64 t; cvta.to.shared.u64 t, %1; cvt.u32.u64 %0, t; }" : "=r"(a) : "l"(p));
    return a;
}
DI unsigned swzA(unsigned o) { return o ^ ((o >> 3) & 0x70u); }
DI unsigned swzB(unsigned o) { return o ^ ((o >> 5) & 0x60u); }

DI void cpasync16(unsigned dst, const void* src) {
    asm volatile("cp.async.cg.shared.global [%0], [%1], 16;"
                 :: "r"(dst), "l"(src) : "memory");
}
// zero-fill variant: src_sz = 16 (copy) or 0 (fill smem with zeros)
DI void cpasync16z(unsigned dst, const void* src, int src_sz) {
    asm volatile("cp.async.cg.shared.global [%0], [%1], 16, %2;"
                 :: "r"(dst), "l"(src), "r"(src_sz) : "memory");
}
DI void cp_commit() { asm volatile("cp.async.commit_group;" ::: "memory"); }
template <int N> DI void cp_wait() {
    asm volatile("cp.async.wait_group %0;" :: "n"(N) : "memory");
}
DI unsigned lds32(unsigned addr) {
    unsigned v;
    asm volatile("ld.shared.b32 %0, [%1];" : "=r"(v) : "r"(addr));
    return v;
}
DI void ldm4(unsigned* r, unsigned addr) {
    asm volatile("ldmatrix.sync.aligned.m8n8.x4.shared.b16 {%0,%1,%2,%3}, [%4];"
                 : "=r"(r[0]), "=r"(r[1]), "=r"(r[2]), "=r"(r[3]) : "r"(addr));
}
DI void mma_tf32(float* d, const unsigned* a, const unsigned* b) {
    asm volatile(
        "mma.sync.aligned.m16n8k8.row.col.f32.tf32.tf32.f32 "
        "{%0,%1,%2,%3}, {%4,%5,%6,%7}, {%8,%9}, {%0,%1,%2,%3};"
        : "+f"(d[0]), "+f"(d[1]), "+f"(d[2]), "+f"(d[3])
        : "r"(a[0]), "r"(a[1]), "r"(a[2]), "r"(a[3]), "r"(b[0]), "r"(b[1]));
}

// ============================================================================
// Setup
// ============================================================================
__global__ void k_setup(const int* __restrict__ sid_raw) {
    __shared__ int nz, counts_s[S_], cursor_s[S_], pad_s[S_];
    const int tid = threadIdx.x;  // 1024
    if (tid == 0) nz = 0;
    if (tid < S_) { counts_s[tid] = 0; cursor_s[tid] = 0; }
    for (int i = tid; i < MAX_TILES * TM; i += 1024) g_perm[i] = -1;
    if (tid < MAX_TILES) g_tile_subject[tid] = -1;
    __syncthreads();
    if (tid < 128 && sid_raw[2 * tid + 1] != 0) atomicOr(&nz, 1);
    __syncthreads();
    const int is64 = (nz == 0);
    int svals[8];
#pragma unroll
    for (int j = 0; j < 8; j++) {
        const int b = tid + j * 1024;
        int s = is64 ? (int)((const long long*)sid_raw)[b] : sid_raw[b];
        s &= (S_ - 1);
        svals[j] = s;
        atomicAdd(&counts_s[s], 1);
    }
    __syncthreads();
    if (tid == 0) {
        int off = 0, tile = 0;
        for (int s = 0; s < S_; s++) {
            pad_s[s] = off;
            const int nt = (counts_s[s] + TM - 1) / TM;
            for (int t = 0; t < nt; t++) g_tile_subject[tile++] = s;
            off += nt * TM;
        }
    }
    __syncthreads();
#pragma unroll
    for (int j = 0; j < 8; j++) {
        const int b = tid + j * 1024;
        const int s = svals[j];
        const int r = atomicAdd(&cursor_s[s], 1);
        g_perm[pad_s[s] + r] = b;
    }
}

// ============================================================================
// Grouped tf32 GEMM — FINAL (R13 configuration, measured optimum, re-verified).
// CTA 128x256, 8 warps (2m x 4n), warp 64x64. 4-stage K=32 cp.async ring
// (wait<2>), fragment double-buffer across chunks, early ISSUE at loop top.
// A gathered directly from x through g_perm (padding rows zero-filled via
// cp.async src_size=0). Both per-thread A swizzle destinations precomputed
// (swzA NOT affine under +16 for odd rows); +8192 row offset IS swizzle-safe.
// Grid: blockIdx.x = n-block (fast), blockIdx.y = tile -> A tiles L2-shared.
// ============================================================================
#define LOADG(KS, BUF, ST)                                                         \
    do {                                                                           \
        const unsigned _aco = ((unsigned)((KS) * 32) + acol_f) ^ axor;             \
        _Pragma("unroll")                                                          \
        for (int _ma = 0; _ma < 4; _ma++)                                          \
            ldm4(afr[BUF][_ma],                                                    \
                 (ST) + (unsigned)((wm * 64 + _ma * 16 + arow_f) * 128) + _aco);   \
        const unsigned _br0 = (ST) + (unsigned)A_BYTES                             \
                              + (unsigned)(((KS) * 8 + kk) * 1024);                \
        _Pragma("unroll")                                                          \
        for (int _na = 0; _na < 8; _na++) {                                        \
            const unsigned _co = bbase + (unsigned)(((_na ^ kk) & 7) << 5);        \
            bfr[BUF][_na][0] = lds32(_br0 + _co);                                  \
            bfr[BUF][_na][1] = lds32(_br0 + 4096 + _co);                           \
        }                                                                          \
    } while (0)

#define MMAALL(BUF)                                                                \
    do {                                                                           \
        _Pragma("unroll")                                                          \
        for (int _ma = 0; _ma < 4; _ma++)                                          \
            _Pragma("unroll")                                                      \
            for (int _na = 0; _na < 8; _na++)                                      \
                mma_tf32(acc[_ma][_na], afr[BUF][_ma], bfr[BUF][_na]);             \
    } while (0)

#define ISSUE_CHUNK(ST, KOFF)                                                      \
    do {                                                                           \
        const float* _a0 = asrc0 + (KOFF);                                         \
        const float* _a1 = asrc1 + (KOFF);                                         \
        cpasync16z((ST) + adst00,        _a0,     az0);                            \
        cpasync16z((ST) + adst01,        _a0 + 4, az0);                            \
        cpasync16z((ST) + adst00 + 8192, _a1,     az1);                            \
        cpasync16z((ST) + adst01 + 8192, _a1 + 4, az1);                            \
        const float* _bs = Ws + (size_t)(KOFF) * OUT_ + n_base;                    \
        _Pragma("unroll")                                                          \
        for (int _i = 0; _i < 8; _i++)                                             \
            cpasync16((ST) + (unsigned)A_BYTES + bdst0 + (unsigned)(_i * 4096),    \
                      _bs + boff0 + _i * 4 * OUT_);                                \
    } while (0)

__global__ void __launch_bounds__(NTHREADS, 1)
k_gemm(const float* __restrict__ x, const float* __restrict__ W,
       const float* __restrict__ bias, float* __restrict__ out) {
    extern __shared__ char smem[];
    const int tile = blockIdx.y;
    const int sub = g_tile_subject[tile];
    if (sub < 0) return;

    const int tid  = threadIdx.x;
    const int wid  = tid >> 5;
    const int lane = tid & 31;
    const int q    = lane >> 2;
    const int kk   = lane & 3;
    const int wm   = wid >> 2;
    const int wn   = wid & 3;
    const int m_base = tile * TM;
    const int n_base = blockIdx.x * TN;
    const unsigned sb = smem_u32(smem);

    const float* Ws = W + (size_t)sub * IN_ * OUT_;

    // ---- A gather setup: rows ar0 = tid>>2 and ar0+64, f4 pair (tid&3)*2 ----
    const int ar0 = tid >> 2;
    const int afc = (tid & 3) * 8;              // float offset of first f4
    const int p0g = g_perm[m_base + ar0];
    const int p1g = g_perm[m_base + ar0 + 64];
    const float* asrc0 = x + (size_t)(p0g < 0 ? 0 : p0g) * IN_ + afc;
    const float* asrc1 = x + (size_t)(p1g < 0 ? 0 : p1g) * IN_ + afc;
    const int az0 = (p0g >= 0) ? 16 : 0;
    const int az1 = (p1g >= 0) ? 16 : 0;
    const unsigned abyte0 = (unsigned)(ar0 * 128 + afc * 4);
    const unsigned adst00 = swzA(abyte0);
    const unsigned adst01 = swzA(abyte0 + 16);

    // B affine cp.async bases
    const unsigned bdst0 = swzB((unsigned)((tid >> 6) * 1024 + (tid & 63) * 16));
    const int      boff0 = (tid >> 6) * OUT_ + (tid & 63) * 4;

    // prologue: chunks 0..2 into stages 0..2
#pragma unroll
    for (int c = 0; c < STAGES - 1; c++) {
        ISSUE_CHUNK(sb + (unsigned)c * STAGE_BYTES, c * KC);
        cp_commit();
    }

    float acc[4][8][4];
#pragma unroll
    for (int i = 0; i < 4; i++)
#pragma unroll
        for (int j = 0; j < 8; j++)
#pragma unroll
            for (int c = 0; c < 4; c++) acc[i][j][c] = 0.f;

    // ldmatrix lane geometry (A)
    const int lt = lane >> 3, lr = lane & 7;
    const int arow_f = ((lt & 1) << 3) + lr;
    const unsigned acol_f = (unsigned)((lt >> 1) << 4);
    const unsigned axor = (unsigned)(lr << 4);
    const unsigned bbase = (unsigned)(wn * 256 + q * 4);

    unsigned afr[2][4][4], bfr[2][8][2];

    cp_wait<2>();            // chunk 0 complete
    __syncthreads();
    LOADG(0, 0, sb);         // prime g0 of chunk 0 into buf 0

    // main loop: ISSUE first (earlier DRAM entry), then g0..g3 with
    // fragment double-buffer pipelined across the chunk boundary.
#pragma unroll 1
    for (int kc = 0; kc < NKC; kc++) {
        const unsigned st = sb + (unsigned)(kc & (STAGES - 1)) * STAGE_BYTES;

        if (kc + STAGES - 1 < NKC) {           // prefetch chunk kc+3 (earliest point)
            const unsigned ns = sb + (unsigned)((kc + STAGES - 1) & (STAGES - 1)) * STAGE_BYTES;
            ISSUE_CHUNK(ns, (kc + STAGES - 1) * KC);
        }
        cp_commit();                           // unconditional: group count exact

        LOADG(1, 1, st);                       // g0
        MMAALL(0);
        LOADG(2, 0, st);                       // g1
        MMAALL(1);
        LOADG(3, 1, st);                       // g2
        MMAALL(0);
        cp_wait<2>();                          // chunk kc+1 complete
        __syncthreads();                       // stage-reuse + visibility barrier
        if (kc + 1 < NKC) {                    // g0 of next chunk under final mma run
            const unsigned ns = sb + (unsigned)((kc + 1) & (STAGES - 1)) * STAGE_BYTES;
            LOADG(0, 0, ns);
        }
        MMAALL(1);                             // g3
    }

    // epilogue: scatter rows through g_perm, add bias
    const float* bias_s = bias + (size_t)sub * OUT_;
    float2 bv[8];
#pragma unroll
    for (int na = 0; na < 8; na++) {
        const int col = n_base + wn * 64 + na * 8 + kk * 2;
        bv[na] = *(const float2*)(bias_s + col);
    }
#pragma unroll
    for (int ma = 0; ma < 4; ma++) {
        const int mr = m_base + wm * 64 + ma * 16 + q;
        const int p0 = g_perm[mr];
        const int p1 = g_perm[mr + 8];
        float* o0 = out + (size_t)(p0 < 0 ? 0 : p0) * OUT_;
        float* o1 = out + (size_t)(p1 < 0 ? 0 : p1) * OUT_;
#pragma unroll
        for (int na = 0; na < 8; na++) {
            const int col = n_base + wn * 64 + na * 8 + kk * 2;
            if (p0 >= 0) {
                float2 v = make_float2(acc[ma][na][0] + bv[na].x,
                                       acc[ma][na][1] + bv[na].y);
                *(float2*)(o0 + col) = v;
            }
            if (p1 >= 0) {
                float2 v = make_float2(acc[ma][na][2] + bv[na].x,
                                       acc[ma][na][3] + bv[na].y);
                *(float2*)(o1 + col) = v;
            }
        }
    }
}

// ============================================================================
// Launch
// ============================================================================
extern "C" void kernel_launch(void* const* d_in, const int* in_sizes, int n_in,
                              void* d_out, int out_size) {
    const float* x    = (const float*)d_in[0];
    const void*  sid  = (const void*)d_in[1];
    const float* W    = (const float*)d_in[2];
    const float* bias = (const float*)d_in[3];
    float* out        = (float*)d_out;

    cudaFuncSetAttribute(k_gemm, cudaFuncAttributeMaxDynamicSharedMemorySize, SMEM_TOTAL);

    k_setup<<<1, 1024>>>((const int*)sid);                  // launch 1
    dim3 gg(NT_N, MAX_TILES);                               // x = n-block, y = tile
    k_gemm<<<gg, NTHREADS, SMEM_TOTAL>>>(x, W, bias, out);  // launch 2
}